// round 1
// baseline (speedup 1.0000x reference)
#include <cuda_runtime.h>
#include <math.h>

#define Bv  4
#define Nn  24
#define NTT 16
#define TSS 48
#define TT  64

// ---------------- device scratch (static: no allocation allowed) ----------------
__device__ float d_eu  [Bv][Nn][TT];                 // exp(unary)
__device__ float d_E0t [Bv][Nn][NTT][NTT][NTT];      // exp(R0[a,h,s<16,c<16]) as [b][h][s][c][a]
__device__ float d_E1t [Bv][Nn][NTT][NTT][NTT];
__device__ float d_U0t [Bv][Nn][Nn][NTT][NTT];       // sum_{c in T48} eu[k][c]*exp(R0[a,h,s,nt+c]) -> [b][h][k][s][a]
__device__ float d_U1t [Bv][Nn][Nn][NTT][NTT];       // sum_{s in T48} eu[k][s]*exp(R1[a,h,nt+s,c]) -> [b][h][k][c][a]
__device__ float d_V0t [Bv][Nn][TT][NTT];            // sum_{s in T48} exp(R0[a,h,nt+s,c])          -> [b][h][c][a]
__device__ float d_V1t [Bv][Nn][TT][NTT];            // sum_{c in T48} exp(R1[a,h,s,nt+c])          -> [b][h][s][a]
__device__ float d_beta [Bv][Nn+1][Nn+1][NTT][Nn];   // scaled prob, absolute head index
__device__ float d_betau[Bv][Nn+1][Nn+1][NTT];       // scaled prob
__device__ float d_Ssc  [Bv][Nn+1][Nn+1];            // log scale per span

// ---------------- kernel 0: exp(unary) ----------------
__global__ void k_eu(const float* __restrict__ unary) {
    int i = blockIdx.x * blockDim.x + threadIdx.x;
    if (i < Bv * Nn * TT) (&d_eu[0][0][0])[i] = expf(unary[i]);
}

// ---------------- kernel 1: rule precompute (block per (b,a,h)) ----------------
__global__ void k_pre(const float* __restrict__ rule) {
    int blk = blockIdx.x;
    int h = blk % Nn;
    int a = (blk / Nn) % NTT;
    int b = blk / (Nn * NTT);
    const float* R = rule + (size_t)(((b * NTT + a) * Nn + h)) * (TT * TT * 2);

    __shared__ float e0t[NTT][TSS];  // exp(R0[s<16][nt+c])
    __shared__ float e1t[TSS][NTT];  // exp(R1[nt+s][c<16])
    __shared__ float eus[Nn][TSS];   // eu[b][k][nt+t]
    int tid = threadIdx.x;

    for (int t = tid; t < Nn * TSS; t += blockDim.x) {
        int k = t / TSS, c = t % TSS;
        eus[k][c] = d_eu[b][k][NTT + c];
    }
    for (int t = tid; t < NTT * NTT; t += blockDim.x) {
        int s = t >> 4, c = t & 15;
        d_E0t[b][h][s][c][a] = expf(R[(s * TT + c) * 2 + 0]);
        d_E1t[b][h][s][c][a] = expf(R[(s * TT + c) * 2 + 1]);
    }
    for (int t = tid; t < NTT * TSS; t += blockDim.x) {
        int s = t / TSS, c = t % TSS;
        e0t[s][c] = expf(R[(s * TT + (NTT + c)) * 2 + 0]);
    }
    for (int t = tid; t < TSS * NTT; t += blockDim.x) {
        int s = t >> 4, c = t & 15;
        e1t[s][c] = expf(R[((NTT + s) * TT + c) * 2 + 1]);
    }
    for (int c = tid; c < TT; c += blockDim.x) {
        float acc = 0.f;
        for (int s = 0; s < TSS; s++) acc += expf(R[((NTT + s) * TT + c) * 2 + 0]);
        d_V0t[b][h][c][a] = acc;
    }
    for (int s = tid; s < TT; s += blockDim.x) {
        float acc = 0.f;
        for (int c = 0; c < TSS; c++) acc += expf(R[(s * TT + NTT + c) * 2 + 1]);
        d_V1t[b][h][s][a] = acc;
    }
    __syncthreads();
    for (int t = tid; t < Nn * NTT; t += blockDim.x) {
        int k = t >> 4, s = t & 15;
        float acc = 0.f;
        #pragma unroll 8
        for (int c = 0; c < TSS; c++) acc += e0t[s][c] * eus[k][c];
        d_U0t[b][h][k][s][a] = acc;
    }
    for (int t = tid; t < Nn * NTT; t += blockDim.x) {
        int k = t >> 4, c = t & 15;
        float acc = 0.f;
        #pragma unroll 8
        for (int s = 0; s < TSS; s++) acc += e1t[s][c] * eus[k][s];
        d_U1t[b][h][k][c][a] = acc;
    }
}

// ---------------- kernel 2: one width level (block per span cell (b,l)) ----------------
__global__ void k_width(int W) {
    int L = Nn - W + 1;
    int b = blockIdx.x / L;
    int l = blockIdx.x % L;
    int r = l + W;
    int tid = threadIdx.x;

    __shared__ float Psm[NTT * NTT * Nn];   // P[s][c][h_local]
    __shared__ float buR[Nn][NTT];          // w_j * betau(right child), j=m-l-1 in [0,W-3]
    __shared__ float buL[Nn][NTT];          // w_j * betau(left child),  j in [1,W-2]
    __shared__ float BL2[NTT][Nn];          // beta[b][l+1][r][c][h]
    __shared__ float BL3[NTT][Nn];          // beta[b][l][r-1][s][h]
    __shared__ float wsp[Nn];
    __shared__ float tmpsm[NTT][Nn];
    __shared__ float red[8];
    __shared__ float sref_s, Msm;

    // ---- split scales ----
    if (tid == 0) {
        float sref = -1e30f;
        for (int j = 0; j <= W - 2; j++) {
            int m = l + 1 + j;
            float sl = (j == 0)     ? 0.f : d_Ssc[b][l][m];
            float sr = (j == W - 2) ? 0.f : d_Ssc[b][m][r];
            wsp[j] = sl + sr;
            sref = fmaxf(sref, sl + sr);
        }
        sref_s = sref;
    }
    __syncthreads();
    if (tid < W - 1) wsp[tid] = expf(wsp[tid] - sref_s);
    __syncthreads();

    if (W >= 3) {
        for (int t = tid; t < (W - 2) * NTT; t += blockDim.x) {
            int j = t >> 4, c = t & 15;
            buR[j][c] = wsp[j] * d_betau[b][l + 1 + j][r][c];
        }
        for (int t = tid; t < (W - 2) * NTT; t += blockDim.x) {
            int j = (t >> 4) + 1, s = t & 15;
            buL[j][s] = wsp[j] * d_betau[b][l][l + 1 + j][s];
        }
        for (int t = tid; t < NTT * W; t += blockDim.x) {
            int c = t / W, hh = t % W;
            BL2[c][hh] = d_beta[b][l + 1][r][c][l + hh];
            BL3[c][hh] = d_beta[b][l][r - 1][c][l + hh];
        }
    }
    __syncthreads();

    float tacc[2] = {0.f, 0.f};
    int nT = NTT * W;

    if (W >= 4) {
        // ---- P0: head-in-left middle splits ----
        for (int t = tid; t < NTT * W; t += blockDim.x) {
            int hh = t % W, s = t / W;
            float accs[NTT];
            #pragma unroll
            for (int c = 0; c < NTT; c++) accs[c] = 0.f;
            for (int j = 1; j <= W - 3; j++) {
                float bl = d_beta[b][l][l + 1 + j][s][l + hh];
                #pragma unroll
                for (int c = 0; c < NTT; c++) accs[c] += bl * buR[j][c];
            }
            #pragma unroll
            for (int c = 0; c < NTT; c++) Psm[(s * NTT + c) * W + hh] = accs[c];
        }
        __syncthreads();
        {
            int p = 0;
            for (int t = tid; t < nT; t += blockDim.x, p++) {
                int a = t & 15, hh = t >> 4;
                const float* E = &d_E0t[b][l + hh][0][0][a];
                const float* P = &Psm[hh];
                float acc = 0.f;
                #pragma unroll 8
                for (int sc = 0; sc < 256; sc++) acc += P[sc * W] * E[sc * NTT];
                tacc[p] += acc;
            }
        }
        __syncthreads();
        // ---- P1: head-in-right middle splits ----
        for (int t = tid; t < NTT * W; t += blockDim.x) {
            int hh = t % W, c = t / W;
            float accs[NTT];
            #pragma unroll
            for (int s = 0; s < NTT; s++) accs[s] = 0.f;
            for (int j = 1; j <= W - 3; j++) {
                float br = d_beta[b][l + 1 + j][r][c][l + hh];
                #pragma unroll
                for (int s = 0; s < NTT; s++) accs[s] += br * buL[j][s];
            }
            #pragma unroll
            for (int s = 0; s < NTT; s++) Psm[(s * NTT + c) * W + hh] = accs[s];
        }
        __syncthreads();
        {
            int p = 0;
            for (int t = tid; t < nT; t += blockDim.x, p++) {
                int a = t & 15, hh = t >> 4;
                const float* E = &d_E1t[b][l + hh][0][0][a];
                const float* P = &Psm[hh];
                float acc = 0.f;
                #pragma unroll 8
                for (int sc = 0; sc < 256; sc++) acc += P[sc * W] * E[sc * NTT];
                tacc[p] += acc;
            }
        }
    }

    // ---- boundary (width-1 child) terms ----
    if (W >= 3) {
        int p = 0;
        for (int t = tid; t < nT; t += blockDim.x, p++) {
            int a = t & 15, hh = t >> 4;
            float acc = 0.f;
            const float* U1 = &d_U1t[b][l + hh][l][0][a];
            float s2 = 0.f;
            #pragma unroll
            for (int c = 0; c < NTT; c++) s2 += U1[c * NTT] * BL2[c][hh];
            acc += wsp[0] * s2;
            const float* U0 = &d_U0t[b][l + hh][r - 1][0][a];
            float s3 = 0.f;
            #pragma unroll
            for (int s = 0; s < NTT; s++) s3 += U0[s * NTT] * BL3[s][hh];
            acc += wsp[W - 2] * s3;
            if (hh == 0) {  // head = l, left child is width-1 terminal (chart value 1)
                float s1 = 0.f;
                #pragma unroll
                for (int c = 0; c < NTT; c++) s1 += d_V0t[b][l][c][a] * buR[0][c];
                acc += s1;
            }
            if (hh == W - 1) {  // head = r-1, right child width-1 terminal
                float s4 = 0.f;
                #pragma unroll
                for (int s = 0; s < NTT; s++) s4 += d_V1t[b][r - 1][s][a] * buL[W - 2][s];
                acc += s4;
            }
            tacc[p] += acc;
        }
    } else {  // W == 2: both children terminal, scale 0, w = 1
        int p = 0;
        for (int t = tid; t < nT; t += blockDim.x, p++) {
            int a = t & 15, hh = t >> 4;
            float acc = 0.f;
            if (hh == 0) {
                #pragma unroll 8
                for (int c = 0; c < TSS; c++)
                    acc += d_eu[b][l + 1][NTT + c] * d_V0t[b][l][NTT + c][a];
            } else {
                #pragma unroll 8
                for (int s = 0; s < TSS; s++)
                    acc += d_eu[b][l][NTT + s] * d_V1t[b][l + 1][NTT + s][a];
            }
            tacc[p] += acc;
        }
    }

    // ---- store tmp, block-max, rescale, commit ----
    float vmax = 0.f;
    {
        int p = 0;
        for (int t = tid; t < nT; t += blockDim.x, p++) {
            int a = t & 15, hh = t >> 4;
            tmpsm[a][hh] = tacc[p];
            vmax = fmaxf(vmax, tacc[p]);
        }
    }
    #pragma unroll
    for (int o = 16; o > 0; o >>= 1) vmax = fmaxf(vmax, __shfl_xor_sync(0xffffffffu, vmax, o));
    if ((tid & 31) == 0) red[tid >> 5] = vmax;
    __syncthreads();
    if (tid < 32) {
        float v = (tid < 8) ? red[tid] : 0.f;
        #pragma unroll
        for (int o = 4; o > 0; o >>= 1) v = fmaxf(v, __shfl_xor_sync(0xffffffffu, v, o));
        if (tid == 0) { Msm = v; d_Ssc[b][l][r] = sref_s + logf(v); }
    }
    __syncthreads();
    float invM = 1.f / Msm;

    for (int t = tid; t < NTT * Nn; t += blockDim.x) {
        int a = t / Nn, habs = t % Nn;
        float v = 0.f;
        if (habs >= l && habs < r) v = tmpsm[a][habs - l] * invM;
        d_beta[b][l][r][a][habs] = v;   // zero-fill outside span => safe unified loops upstream
    }
    for (int a = tid; a < NTT; a += blockDim.x) {
        float accu = 0.f;
        for (int hh = 0; hh < W; hh++) accu += tmpsm[a][hh] * d_eu[b][l + hh][a];
        d_betau[b][l][r][a] = accu * invM;
    }
}

// ---------------- kernel 3: root reduction ----------------
__global__ void k_final(const float* __restrict__ root, float* __restrict__ out) {
    int b = threadIdx.x;
    if (b < Bv) {
        float acc = 0.f;
        for (int a = 0; a < NTT; a++) acc += d_betau[b][0][Nn][a] * expf(root[b * NTT + a]);
        out[b] = d_Ssc[b][0][Nn] + logf(acc);
    }
}

// ---------------- launch ----------------
extern "C" void kernel_launch(void* const* d_in, const int* in_sizes, int n_in,
                              void* d_out, int out_size) {
    const float* unary = nullptr;
    const float* rule  = nullptr;
    const float* root  = nullptr;
    for (int i = 0; i < n_in; i++) {
        if (in_sizes[i] == Bv * Nn * TT)                 unary = (const float*)d_in[i];
        else if (in_sizes[i] == Bv * NTT * Nn * TT * TT * 2) rule = (const float*)d_in[i];
        else if (in_sizes[i] == Bv * NTT)                root = (const float*)d_in[i];
    }

    k_eu<<<(Bv * Nn * TT + 255) / 256, 256>>>(unary);
    k_pre<<<Bv * NTT * Nn, 256>>>(rule);
    for (int W = 2; W <= Nn; W++) {
        int L = Nn - W + 1;
        k_width<<<Bv * L, 256>>>(W);
    }
    k_final<<<1, 32>>>(root, (float*)d_out);
}

// round 2
// speedup vs baseline: 1.9237x; 1.9237x over previous
#include <cuda_runtime.h>
#include <math.h>

#define Bv  4
#define Nn  24
#define NTT 16
#define TSS 48
#define TT  64
#define GBLK 92
#define THR 384

// ---------------- device scratch ----------------
__device__ float d_eu  [Bv][Nn][TT];                 // exp(unary)
__device__ float d_E0t [Bv][Nn][NTT][NTT][NTT];      // exp(R0[a,h,s<16,c<16]) as [b][h][s][c][a]
__device__ float d_E1t [Bv][Nn][NTT][NTT][NTT];
__device__ float d_U0t [Bv][Nn][Nn][NTT][NTT];       // [b][h][k][s][a]
__device__ float d_U1t [Bv][Nn][Nn][NTT][NTT];       // [b][h][k][c][a]
__device__ float d_V0t [Bv][Nn][TT][NTT];            // [b][h][c][a]
__device__ float d_V1t [Bv][Nn][TT][NTT];            // [b][h][s][a]
__device__ float d_beta [Bv][Nn+1][Nn+1][NTT][Nn];
__device__ float d_betau[Bv][Nn+1][Nn+1][NTT];
__device__ float d_Ssc  [Bv][Nn+1][Nn+1];
__device__ int           g_cnt;
__device__ volatile int  g_gen;

// ---------------- kernel 0: exp(unary) + barrier reset ----------------
__global__ void k_eu(const float* __restrict__ unary) {
    int i = blockIdx.x * blockDim.x + threadIdx.x;
    if (i == 0) { g_cnt = 0; g_gen = 0; }
    if (i < Bv * Nn * TT) (&d_eu[0][0][0])[i] = __expf(unary[i]);
}

// ---------------- kernel 1: rule precompute (block per (b,a,h)) ----------------
__global__ void __launch_bounds__(256) k_pre(const float* __restrict__ rule) {
    int blk = blockIdx.x;
    int h = blk % Nn;
    int a = (blk / Nn) % NTT;
    int b = blk / (Nn * NTT);
    const float2* R2 = (const float2*)(rule + (size_t)((b * NTT + a) * Nn + h) * (TT * TT * 2));

    __shared__ float Er0[TT][TT];   // exp(R0[s][c])
    __shared__ float Er1[TT][TT];   // exp(R1[s][c])
    __shared__ float eus[Nn][49];   // padded to kill bank conflicts
    int tid = threadIdx.x;

    for (int e = tid; e < TT * TT; e += 256) {
        float2 v = R2[e];
        int s = e >> 6, c = e & 63;
        Er0[s][c] = __expf(v.x);
        Er1[s][c] = __expf(v.y);
    }
    for (int t = tid; t < Nn * TSS; t += 256) {
        int k = t / TSS, c = t % TSS;
        eus[k][c] = d_eu[b][k][NTT + c];
    }
    __syncthreads();

    // E tables (NT x NT corner)
    {
        int s = tid >> 4, c = tid & 15;
        if (tid < 256) {
            d_E0t[b][h][s][c][a] = Er0[s][c];
            d_E1t[b][h][s][c][a] = Er1[s][c];
        }
    }
    // V tables: V0[c] = sum_{s in T} Er0[s][c];  V1[s] = sum_{c in T} Er1[s][c]
    if (tid < 128) {
        int x = tid & 63;
        float acc = 0.f;
        if (tid < 64) {
            #pragma unroll 8
            for (int s = NTT; s < TT; s++) acc += Er0[s][x];
            d_V0t[b][h][x][a] = acc;
        } else {
            #pragma unroll 8
            for (int c = NTT; c < TT; c++) acc += Er1[x][c];
            d_V1t[b][h][x][a] = acc;
        }
    }
    // U tables: U0[k][s] = sum_c Er0[s][nt+c]*eus[k][c]; U1[k][c] = sum_s Er1[nt+s][c]*eus[k][s]
    for (int t = tid; t < 2 * Nn * NTT; t += 256) {
        int which = t / (Nn * NTT);
        int u = t % (Nn * NTT);
        int k = u % Nn, x = u / Nn;   // x = s (U0) or c (U1)
        float acc = 0.f;
        if (which == 0) {
            #pragma unroll 8
            for (int c = 0; c < TSS; c++) acc += Er0[x][NTT + c] * eus[k][c];
            d_U0t[b][h][k][x][a] = acc;
        } else {
            #pragma unroll 8
            for (int s = 0; s < TSS; s++) acc += Er1[NTT + s][x] * eus[k][s];
            d_U1t[b][h][k][x][a] = acc;
        }
    }
}

// ---------------- kernel 2: persistent chart kernel (all widths + final) ----------------
__device__ __forceinline__ void grid_sync() {
    __syncthreads();
    if (threadIdx.x == 0) {
        __threadfence();                       // release chart writes to L2
        int g = g_gen;
        if (atomicAdd(&g_cnt, 1) == GBLK - 1) {
            g_cnt = 0;
            __threadfence();
            g_gen = g + 1;
        } else {
            while (g_gen == g) { __nanosleep(64); }
        }
        __threadfence();                       // acquire
    }
    __syncthreads();
}

__global__ void __launch_bounds__(THR, 1) k_chart(const float* __restrict__ root,
                                                  float* __restrict__ out) {
    extern __shared__ float Psm[];   // [2][256][W]
    __shared__ float buR[Nn][NTT];
    __shared__ float buL[Nn][NTT];
    __shared__ float BL2[NTT][Nn];
    __shared__ float BL3[NTT][Nn];
    __shared__ float wsp[Nn];
    __shared__ float tmpsm[NTT][Nn];
    __shared__ float Ppart[THR];
    __shared__ float red[12];
    __shared__ float sref_s, Msm;
    int tid = threadIdx.x;

    for (int W = 2; W <= Nn; W++) {
        int L = Nn - W + 1;
        if ((int)blockIdx.x < Bv * L) {
            int b = blockIdx.x / L, l = blockIdx.x % L, r = l + W;
            int nT = NTT * W;

            // ---- split-scale weights (parallel) ----
            if (tid < W - 1) {
                int j = tid, m = l + 1 + j;
                float sl = (j == 0)     ? 0.f : __ldcg(&d_Ssc[b][l][m]);
                float sr = (j == W - 2) ? 0.f : __ldcg(&d_Ssc[b][m][r]);
                wsp[j] = sl + sr;
            }
            __syncthreads();
            if (tid == 0) {
                float s = -1e30f;
                for (int j = 0; j <= W - 2; j++) s = fmaxf(s, wsp[j]);
                sref_s = s;
            }
            __syncthreads();
            if (tid < W - 1) wsp[tid] = __expf(wsp[tid] - sref_s);
            __syncthreads();

            // ---- child charts into smem ----
            if (W >= 3) {
                if (tid < (W - 2) * NTT) {
                    int j = tid >> 4, c = tid & 15;
                    buR[j][c]     = wsp[j]     * __ldcg(&d_betau[b][l + 1 + j][r][c]);
                    buL[j + 1][c] = wsp[j + 1] * __ldcg(&d_betau[b][l][l + 2 + j][c]);
                }
                if (tid < nT) {
                    int c = tid / W, hh = tid % W;
                    BL2[c][hh] = __ldcg(&d_beta[b][l + 1][r][c][l + hh]);
                    BL3[c][hh] = __ldcg(&d_beta[b][l][r - 1][c][l + hh]);
                }
            }
            __syncthreads();

            float tacc = 0.f;
            float* P0 = Psm;
            float* P1 = Psm + 256 * W;

            if (W >= 4) {
                // ---- build P0 and P1 (middle splits), fused ----
                if (tid < nT) {
                    int hh = tid % W, x = tid / W;   // x: left-sym for P0, right-sym for P1
                    float a0[NTT], a1[NTT];
                    #pragma unroll
                    for (int c = 0; c < NTT; c++) { a0[c] = 0.f; a1[c] = 0.f; }
                    for (int j = 1; j <= W - 3; j++) {
                        float bl = __ldcg(&d_beta[b][l][l + 1 + j][x][l + hh]);
                        float br = __ldcg(&d_beta[b][l + 1 + j][r][x][l + hh]);
                        #pragma unroll
                        for (int c = 0; c < NTT; c++) {
                            a0[c] += bl * buR[j][c];
                            a1[c] += br * buL[j][c];
                        }
                    }
                    #pragma unroll
                    for (int c = 0; c < NTT; c++) {
                        P0[(x * NTT + c) * W + hh] = a0[c];   // P0[s][c][hh]
                        P1[(c * NTT + x) * W + hh] = a1[c];   // P1[s][c][hh], a1[c] ~ s=c role
                    }
                }
                __syncthreads();

                // ---- fused dual contraction with chain splitting ----
                int SPLIT = (W >= 13) ? 1 : ((W >= 7) ? 2 : 4);
                int CH = 256 / SPLIT;
                if (tid < nT * SPLIT) {
                    int u = tid % nT, part = tid / nT;
                    int a = u & 15, hh = u >> 4;
                    const float* E0 = &d_E0t[b][l + hh][0][0][a];
                    const float* E1 = &d_E1t[b][l + hh][0][0][a];
                    const float* p0 = P0 + hh;
                    const float* p1 = P1 + hh;
                    int base = part * CH;
                    float acc0 = 0.f, acc1 = 0.f;
                    #pragma unroll 8
                    for (int i = 0; i < CH; i++) {
                        int sc = base + i;
                        acc0 += p0[sc * W] * __ldg(E0 + sc * NTT);
                        acc1 += p1[sc * W] * __ldg(E1 + sc * NTT);
                    }
                    Ppart[tid] = acc0 + acc1;
                }
                __syncthreads();
                if (tid < nT) {
                    float s = Ppart[tid];
                    for (int k = 1; k < SPLIT; k++) s += Ppart[tid + k * nT];
                    tacc += s;
                }
            }

            // ---- boundary (width-1 child) terms ----
            if (W >= 3) {
                if (tid < nT) {
                    int a = tid & 15, hh = tid >> 4;
                    const float* U1 = &d_U1t[b][l + hh][l][0][a];
                    const float* U0 = &d_U0t[b][l + hh][r - 1][0][a];
                    float s2 = 0.f, s3 = 0.f;
                    #pragma unroll
                    for (int c = 0; c < NTT; c++) {
                        s2 += __ldg(U1 + c * NTT) * BL2[c][hh];
                        s3 += __ldg(U0 + c * NTT) * BL3[c][hh];
                    }
                    tacc += wsp[0] * s2 + wsp[W - 2] * s3;
                    if (hh == 0) {
                        float s1 = 0.f;
                        #pragma unroll
                        for (int c = 0; c < NTT; c++)
                            s1 += __ldg(&d_V0t[b][l][c][a]) * buR[0][c];
                        tacc += s1;
                    }
                    if (hh == W - 1) {
                        float s4 = 0.f;
                        #pragma unroll
                        for (int c = 0; c < NTT; c++)
                            s4 += __ldg(&d_V1t[b][r - 1][c][a]) * buL[W - 2][c];
                        tacc += s4;
                    }
                }
            } else {  // W == 2: both children terminal
                if (tid < nT) {
                    int a = tid & 15, hh = tid >> 4;
                    float acc = 0.f;
                    if (hh == 0) {
                        #pragma unroll 8
                        for (int c = 0; c < TSS; c++)
                            acc += __ldg(&d_eu[b][l + 1][NTT + c]) * __ldg(&d_V0t[b][l][NTT + c][a]);
                    } else {
                        #pragma unroll 8
                        for (int c = 0; c < TSS; c++)
                            acc += __ldg(&d_eu[b][l][NTT + c]) * __ldg(&d_V1t[b][l + 1][NTT + c][a]);
                    }
                    tacc += acc;
                }
            }

            // ---- max, rescale, commit ----
            float vmax = 0.f;
            if (tid < nT) {
                int a = tid & 15, hh = tid >> 4;
                tmpsm[a][hh] = tacc;
                vmax = tacc;
            }
            #pragma unroll
            for (int o = 16; o > 0; o >>= 1) vmax = fmaxf(vmax, __shfl_xor_sync(0xffffffffu, vmax, o));
            if ((tid & 31) == 0) red[tid >> 5] = vmax;
            __syncthreads();
            if (tid < 32) {
                float v = (tid < 12) ? red[tid] : 0.f;
                #pragma unroll
                for (int o = 8; o > 0; o >>= 1) v = fmaxf(v, __shfl_xor_sync(0xffffffffu, v, o));
                if (tid == 0) { Msm = v; __stcg(&d_Ssc[b][l][r], sref_s + logf(v)); }
            }
            __syncthreads();
            float invM = 1.f / Msm;
            {
                int a = tid / Nn, habs = tid % Nn;   // THR == 16*24 exactly
                float v = 0.f;
                if (habs >= l && habs < r) v = tmpsm[a][habs - l] * invM;
                __stcg(&d_beta[b][l][r][a][habs], v);
            }
            if (tid < NTT) {
                float accu = 0.f;
                for (int hh = 0; hh < W; hh++)
                    accu += tmpsm[tid][hh] * __ldg(&d_eu[b][l + hh][tid]);
                __stcg(&d_betau[b][l][r][tid], accu * invM);
            }
        }
        grid_sync();
    }

    // ---- root reduction ----
    if (blockIdx.x == 0 && tid < Bv) {
        float acc = 0.f;
        for (int a = 0; a < NTT; a++)
            acc += __ldcg(&d_betau[tid][0][Nn][a]) * expf(root[tid * NTT + a]);
        out[tid] = __ldcg(&d_Ssc[tid][0][Nn]) + logf(acc);
    }
}

// ---------------- launch ----------------
extern "C" void kernel_launch(void* const* d_in, const int* in_sizes, int n_in,
                              void* d_out, int out_size) {
    const float* unary = nullptr;
    const float* rule  = nullptr;
    const float* root  = nullptr;
    for (int i = 0; i < n_in; i++) {
        if (in_sizes[i] == Bv * Nn * TT)                      unary = (const float*)d_in[i];
        else if (in_sizes[i] == Bv * NTT * Nn * TT * TT * 2)  rule  = (const float*)d_in[i];
        else if (in_sizes[i] == Bv * NTT)                     root  = (const float*)d_in[i];
    }

    static bool attr_done = false;   // idempotent attribute set (no work, allowed)
    cudaFuncSetAttribute(k_chart, cudaFuncAttributeMaxDynamicSharedMemorySize, 49152);
    (void)attr_done;

    k_eu<<<(Bv * Nn * TT + 255) / 256, 256>>>(unary);
    k_pre<<<Bv * NTT * Nn, 256>>>(rule);
    k_chart<<<GBLK, THR, 2 * 256 * Nn * sizeof(float)>>>(root, (float*)d_out);
}